// round 1
// baseline (speedup 1.0000x reference)
#include <cuda_runtime.h>
#include <cuda_bf16.h>

// ---------------------------------------------------------------------------
// RGBLambertianRendererWithVisibility
//   N=500000 samples, L=64 lights, R=4096 rays (all derived from sizes).
//   Pass 1: fused shade + segment scatter-add (warp per sample).
//   Pass 2: background blend + sRGB (R threads).
// Scratch: __device__ accumulator [MAX_RAYS][4] = (r,g,b,weight).
// ---------------------------------------------------------------------------

#define MAX_RAYS 65536
__device__ float g_acc[MAX_RAYS * 4];
__device__ int   g_idx_is64;

// --- zero the accumulator (graph-capturable; no memset-on-symbol) ---------
__global__ void zero_acc_kernel(int n4) {
    int i = blockIdx.x * blockDim.x + threadIdx.x;
    if (i < n4) g_acc[i] = 0.0f;
}

// --- detect whether ray_indices is int64 or int32 --------------------------
// ray_indices is sorted, values in [0, R). If stored as int64 (little-endian),
// the int32 word stream is [lo0, 0, lo1, 0, ...]. We inspect words in the
// middle of the first N words (in-bounds for BOTH dtypes): for int32 data
// those words are values near N/(2*avg) >> 0 (never zero); for int64 data
// every odd word is zero. Deterministic pure function of the input.
__global__ void detect_idx_kernel(const int* __restrict__ words, int n_words_safe) {
    if (blockIdx.x == 0 && threadIdx.x == 0) {
        int end = n_words_safe;         // = N (element count), safe for both dtypes
        int start = end - 2048; if (start < 0) start = 0;
        int zeros = 0;
        for (int i = start; i < end; ++i) zeros += (words[i] == 0);
        g_idx_is64 = (zeros > 0) ? 1 : 0;
    }
}

// --- main fused pass: one warp per sample ----------------------------------
__global__ void shade_kernel(const float* __restrict__ albedos,
                             const float* __restrict__ normals,
                             const float* __restrict__ ldir,
                             const float* __restrict__ lcol,
                             const float* __restrict__ vis,
                             const float* __restrict__ weights,
                             const void*  __restrict__ ray_idx,
                             int N, int L) {
    int gwarp = (blockIdx.x * blockDim.x + threadIdx.x) >> 5;
    int lane  = threadIdx.x & 31;
    if (gwarp >= N) return;

    // all lanes load the same normal -> L1 broadcast
    float nx = normals[gwarp * 3 + 0];
    float ny = normals[gwarp * 3 + 1];
    float nz = normals[gwarp * 3 + 2];

    const float* ldp = ldir + (size_t)gwarp * L * 3;
    const float* lcp = lcol + (size_t)gwarp * L * 3;
    const float* vp  = vis  + (size_t)gwarp * L;

    float s0 = 0.f, s1 = 0.f, s2 = 0.f;
    int cnt = 0;

    for (int j = lane; j < L; j += 32) {
        float dx = ldp[j * 3 + 0];
        float dy = ldp[j * 3 + 1];
        float dz = ldp[j * 3 + 2];
        float d  = fmaf(nx, dx, fmaf(ny, dy, nz * dz));
        cnt += (d > 0.f) ? 1 : 0;
        d = fminf(fmaxf(d, 0.f), 1.f);
        float dv = d * vp[j];
        s0 = fmaf(dv, lcp[j * 3 + 0], s0);
        s1 = fmaf(dv, lcp[j * 3 + 1], s1);
        s2 = fmaf(dv, lcp[j * 3 + 2], s2);
    }

    // warp reduction
    #pragma unroll
    for (int off = 16; off; off >>= 1) {
        s0  += __shfl_xor_sync(0xFFFFFFFFu, s0,  off);
        s1  += __shfl_xor_sync(0xFFFFFFFFu, s1,  off);
        s2  += __shfl_xor_sync(0xFFFFFFFFu, s2,  off);
        cnt += __shfl_xor_sync(0xFFFFFFFFu, cnt, off);
    }

    if (lane == 0) {
        float c   = (cnt > 0) ? (float)cnt : 1.0f;
        float inv = 1.0f / c;
        float w   = weights[gwarp];
        int r;
        if (g_idx_is64) r = (int)((const long long*)ray_idx)[gwarp];
        else            r = ((const int*)ray_idx)[gwarp];
        float a0 = albedos[gwarp * 3 + 0];
        float a1 = albedos[gwarp * 3 + 1];
        float a2 = albedos[gwarp * 3 + 2];
        atomicAdd(&g_acc[r * 4 + 0], w * a0 * s0 * inv);
        atomicAdd(&g_acc[r * 4 + 1], w * a1 * s1 * inv);
        atomicAdd(&g_acc[r * 4 + 2], w * a2 * s2 * inv);
        atomicAdd(&g_acc[r * 4 + 3], w);
    }
}

// --- finalize: background blend + sRGB --------------------------------------
__global__ void finalize_kernel(const float* __restrict__ bg,
                                float* __restrict__ out, int R) {
    int r = blockIdx.x * blockDim.x + threadIdx.x;
    if (r >= R) return;
    float aw = g_acc[r * 4 + 3];
    float one_m = 1.0f - aw;
    #pragma unroll
    for (int c = 0; c < 3; ++c) {
        float x = g_acc[r * 4 + c] + bg[r * 3 + c] * one_m;
        float safe = fmaxf(x, 1e-8f);
        float y = (x <= 0.0031308f) ? (12.92f * x)
                                    : (1.055f * powf(safe, 1.0f / 2.4f) - 0.055f);
        out[r * 3 + c] = y;
    }
}

extern "C" void kernel_launch(void* const* d_in, const int* in_sizes, int n_in,
                              void* d_out, int out_size) {
    const float* albedos = (const float*)d_in[0];   // [N,3]
    const float* normals = (const float*)d_in[1];   // [N,3]
    const float* ldir    = (const float*)d_in[2];   // [N,L,3]
    const float* lcol    = (const float*)d_in[3];   // [N,L,3]
    const float* vis     = (const float*)d_in[4];   // [N,L,1]
    const float* bg      = (const float*)d_in[5];   // [R,3]
    const float* weights = (const float*)d_in[6];   // [N,1]
    const void*  ray_idx = (const void*) d_in[7];   // [N] int32 or int64
    float* out = (float*)d_out;                     // [R,3]

    int N = in_sizes[0] / 3;
    int L = (N > 0) ? in_sizes[2] / (N * 3) : 1;
    int R = out_size / 3;
    if (R > MAX_RAYS) R = MAX_RAYS;

    // 1) detect index dtype (tiny, deterministic)
    detect_idx_kernel<<<1, 32>>>((const int*)ray_idx, in_sizes[7]);

    // 2) zero accumulators
    int n4 = R * 4;
    zero_acc_kernel<<<(n4 + 255) / 256, 256>>>(n4);

    // 3) fused shade + scatter (warp per sample, 8 warps/block)
    int warps_per_block = 8;
    int blocks = (N + warps_per_block - 1) / warps_per_block;
    shade_kernel<<<blocks, warps_per_block * 32>>>(
        albedos, normals, ldir, lcol, vis, weights, ray_idx, N, L);

    // 4) blend + sRGB
    finalize_kernel<<<(R + 255) / 256, 256>>>(bg, out, R);
}

// round 2
// speedup vs baseline: 1.3725x; 1.3725x over previous
#include <cuda_runtime.h>
#include <cuda_bf16.h>

// ---------------------------------------------------------------------------
// RGBLambertianRendererWithVisibility — R2
//   Half-warp (16 lanes) per sample; each sub-lane owns 4 lights = 3 float4
//   from ldir + 3 float4 from lcol + 1 float4 of vis  ->  all LDG.128.
// ---------------------------------------------------------------------------

#define MAX_RAYS 65536
__device__ float g_acc[MAX_RAYS * 4];
__device__ int   g_idx_is64;

__global__ void zero_acc_kernel(int n4) {
    int i = blockIdx.x * blockDim.x + threadIdx.x;
    if (i < n4) g_acc[i] = 0.0f;
}

// Detect int64 vs int32 ray_indices (sorted, values < R). For int64 data the
// word stream interleaves zero high-halves; for int32 the tail words are the
// largest indices (nonzero). Deterministic pure function of input.
__global__ void detect_idx_kernel(const int* __restrict__ words, int n_words_safe) {
    if (blockIdx.x == 0 && threadIdx.x == 0) {
        int end = n_words_safe;
        int start = end - 2048; if (start < 0) start = 0;
        int zeros = 0;
        for (int i = start; i < end; ++i) zeros += (words[i] == 0);
        g_idx_is64 = (zeros > 0) ? 1 : 0;
    }
}

// --- main fused pass: half-warp per sample, L must be 64 -------------------
__global__ __launch_bounds__(256) void shade_kernel(
        const float* __restrict__ albedos,
        const float* __restrict__ normals,
        const float* __restrict__ ldir,
        const float* __restrict__ lcol,
        const float* __restrict__ vis,
        const float* __restrict__ weights,
        const void*  __restrict__ ray_idx,
        int N) {
    int gwarp = (blockIdx.x * blockDim.x + threadIdx.x) >> 5;
    int lane  = threadIdx.x & 31;
    int half  = lane >> 4;          // 0/1 : which sample within the warp
    int sub   = lane & 15;          // 0..15 : sub-lane within sample
    int s     = gwarp * 2 + half;   // sample id
    if (s >= N) return;

    // 64 lights * 3 floats = 192 floats = 48 float4 per row (768B aligned)
    const float4* ldp = (const float4*)(ldir + (size_t)s * 192);
    const float4* lcp = (const float4*)(lcol + (size_t)s * 192);
    const float4* vp  = (const float4*)(vis  + (size_t)s * 64);

    // 7 independent LDG.128 — front-batched for MLP
    float4 d0 = ldp[sub * 3 + 0];
    float4 d1 = ldp[sub * 3 + 1];
    float4 d2 = ldp[sub * 3 + 2];
    float4 c0 = lcp[sub * 3 + 0];
    float4 c1 = lcp[sub * 3 + 1];
    float4 c2 = lcp[sub * 3 + 2];
    float4 v  = vp[sub];

    float nx = normals[s * 3 + 0];   // broadcast within half-warp
    float ny = normals[s * 3 + 1];
    float nz = normals[s * 3 + 2];

    // lights handled by this sub-lane: 4*sub .. 4*sub+3
    // l0=(d0.x,d0.y,d0.z) l1=(d0.w,d1.x,d1.y) l2=(d1.z,d1.w,d2.x) l3=(d2.y,d2.z,d2.w)
    float t0 = fmaf(nx, d0.x, fmaf(ny, d0.y, nz * d0.z));
    float t1 = fmaf(nx, d0.w, fmaf(ny, d1.x, nz * d1.y));
    float t2 = fmaf(nx, d1.z, fmaf(ny, d1.w, nz * d2.x));
    float t3 = fmaf(nx, d2.y, fmaf(ny, d2.z, nz * d2.w));

    int cnt = (t0 > 0.f) + (t1 > 0.f) + (t2 > 0.f) + (t3 > 0.f);

    t0 = fminf(fmaxf(t0, 0.f), 1.f) * v.x;
    t1 = fminf(fmaxf(t1, 0.f), 1.f) * v.y;
    t2 = fminf(fmaxf(t2, 0.f), 1.f) * v.z;
    t3 = fminf(fmaxf(t3, 0.f), 1.f) * v.w;

    // colors: l0=(c0.x,c0.y,c0.z) l1=(c0.w,c1.x,c1.y) l2=(c1.z,c1.w,c2.x) l3=(c2.y,c2.z,c2.w)
    float s0 = fmaf(t0, c0.x, fmaf(t1, c0.w, fmaf(t2, c1.z, t3 * c2.y)));
    float s1 = fmaf(t0, c0.y, fmaf(t1, c1.x, fmaf(t2, c1.w, t3 * c2.z)));
    float s2 = fmaf(t0, c0.z, fmaf(t1, c1.y, fmaf(t2, c2.x, t3 * c2.w)));

    // half-warp reduction (xor offsets stay within the 16-lane group)
    #pragma unroll
    for (int off = 8; off; off >>= 1) {
        s0  += __shfl_xor_sync(0xFFFFFFFFu, s0,  off);
        s1  += __shfl_xor_sync(0xFFFFFFFFu, s1,  off);
        s2  += __shfl_xor_sync(0xFFFFFFFFu, s2,  off);
        cnt += __shfl_xor_sync(0xFFFFFFFFu, cnt, off);
    }

    if (sub == 0) {
        float c   = (cnt > 0) ? (float)cnt : 1.0f;
        float inv = 1.0f / c;
        float w   = weights[s];
        int r;
        if (g_idx_is64) r = (int)((const long long*)ray_idx)[s];
        else            r = ((const int*)ray_idx)[s];
        float a0 = albedos[s * 3 + 0];
        float a1 = albedos[s * 3 + 1];
        float a2 = albedos[s * 3 + 2];
        atomicAdd(&g_acc[r * 4 + 0], w * a0 * s0 * inv);
        atomicAdd(&g_acc[r * 4 + 1], w * a1 * s1 * inv);
        atomicAdd(&g_acc[r * 4 + 2], w * a2 * s2 * inv);
        atomicAdd(&g_acc[r * 4 + 3], w);
    }
}

__global__ void finalize_kernel(const float* __restrict__ bg,
                                float* __restrict__ out, int R) {
    int r = blockIdx.x * blockDim.x + threadIdx.x;
    if (r >= R) return;
    float aw = g_acc[r * 4 + 3];
    float one_m = 1.0f - aw;
    #pragma unroll
    for (int c = 0; c < 3; ++c) {
        float x = g_acc[r * 4 + c] + bg[r * 3 + c] * one_m;
        float safe = fmaxf(x, 1e-8f);
        float y = (x <= 0.0031308f) ? (12.92f * x)
                                    : (1.055f * powf(safe, 1.0f / 2.4f) - 0.055f);
        out[r * 3 + c] = y;
    }
}

// Fallback for L != 64 (generic, scalar; matches R1 logic)
__global__ void shade_kernel_generic(
        const float* __restrict__ albedos,
        const float* __restrict__ normals,
        const float* __restrict__ ldir,
        const float* __restrict__ lcol,
        const float* __restrict__ vis,
        const float* __restrict__ weights,
        const void*  __restrict__ ray_idx,
        int N, int L) {
    int gwarp = (blockIdx.x * blockDim.x + threadIdx.x) >> 5;
    int lane  = threadIdx.x & 31;
    if (gwarp >= N) return;
    float nx = normals[gwarp * 3 + 0];
    float ny = normals[gwarp * 3 + 1];
    float nz = normals[gwarp * 3 + 2];
    const float* ldp = ldir + (size_t)gwarp * L * 3;
    const float* lcp = lcol + (size_t)gwarp * L * 3;
    const float* vp  = vis  + (size_t)gwarp * L;
    float s0 = 0.f, s1 = 0.f, s2 = 0.f;
    int cnt = 0;
    for (int j = lane; j < L; j += 32) {
        float dx = ldp[j * 3 + 0], dy = ldp[j * 3 + 1], dz = ldp[j * 3 + 2];
        float d  = fmaf(nx, dx, fmaf(ny, dy, nz * dz));
        cnt += (d > 0.f) ? 1 : 0;
        d = fminf(fmaxf(d, 0.f), 1.f);
        float dv = d * vp[j];
        s0 = fmaf(dv, lcp[j * 3 + 0], s0);
        s1 = fmaf(dv, lcp[j * 3 + 1], s1);
        s2 = fmaf(dv, lcp[j * 3 + 2], s2);
    }
    #pragma unroll
    for (int off = 16; off; off >>= 1) {
        s0  += __shfl_xor_sync(0xFFFFFFFFu, s0,  off);
        s1  += __shfl_xor_sync(0xFFFFFFFFu, s1,  off);
        s2  += __shfl_xor_sync(0xFFFFFFFFu, s2,  off);
        cnt += __shfl_xor_sync(0xFFFFFFFFu, cnt, off);
    }
    if (lane == 0) {
        float c   = (cnt > 0) ? (float)cnt : 1.0f;
        float inv = 1.0f / c;
        float w   = weights[gwarp];
        int r;
        if (g_idx_is64) r = (int)((const long long*)ray_idx)[gwarp];
        else            r = ((const int*)ray_idx)[gwarp];
        atomicAdd(&g_acc[r * 4 + 0], w * albedos[gwarp * 3 + 0] * s0 * inv);
        atomicAdd(&g_acc[r * 4 + 1], w * albedos[gwarp * 3 + 1] * s1 * inv);
        atomicAdd(&g_acc[r * 4 + 2], w * albedos[gwarp * 3 + 2] * s2 * inv);
        atomicAdd(&g_acc[r * 4 + 3], w);
    }
}

extern "C" void kernel_launch(void* const* d_in, const int* in_sizes, int n_in,
                              void* d_out, int out_size) {
    const float* albedos = (const float*)d_in[0];   // [N,3]
    const float* normals = (const float*)d_in[1];   // [N,3]
    const float* ldir    = (const float*)d_in[2];   // [N,L,3]
    const float* lcol    = (const float*)d_in[3];   // [N,L,3]
    const float* vis     = (const float*)d_in[4];   // [N,L,1]
    const float* bg      = (const float*)d_in[5];   // [R,3]
    const float* weights = (const float*)d_in[6];   // [N,1]
    const void*  ray_idx = (const void*) d_in[7];   // [N] int32 or int64
    float* out = (float*)d_out;                     // [R,3]

    int N = in_sizes[0] / 3;
    int L = (N > 0) ? in_sizes[2] / (N * 3) : 1;
    int R = out_size / 3;
    if (R > MAX_RAYS) R = MAX_RAYS;

    detect_idx_kernel<<<1, 32>>>((const int*)ray_idx, in_sizes[7]);

    int n4 = R * 4;
    zero_acc_kernel<<<(n4 + 255) / 256, 256>>>(n4);

    if (L == 64) {
        // 2 samples per warp, 8 warps per block -> 16 samples per block
        int samples_per_block = 16;
        int blocks = (N + samples_per_block - 1) / samples_per_block;
        shade_kernel<<<blocks, 256>>>(
            albedos, normals, ldir, lcol, vis, weights, ray_idx, N);
    } else {
        int blocks = (N + 7) / 8;
        shade_kernel_generic<<<blocks, 256>>>(
            albedos, normals, ldir, lcol, vis, weights, ray_idx, N, L);
    }

    finalize_kernel<<<(R + 255) / 256, 256>>>(bg, out, R);
}

// round 3
// speedup vs baseline: 1.6008x; 1.1664x over previous
#include <cuda_runtime.h>
#include <cuda_bf16.h>

// ---------------------------------------------------------------------------
// RGBLambertianRendererWithVisibility — R3
//   R2 + parallel dtype detection (was ~80us serial single-thread loop)
//   + evict-streaming loads for the read-once light data.
// ---------------------------------------------------------------------------

#define MAX_RAYS 65536
__device__ float g_acc[MAX_RAYS * 4];
__device__ int   g_idx_is64;

// Zero accumulators AND the detection flag.
__global__ void zero_acc_kernel(int n4) {
    int i = blockIdx.x * blockDim.x + threadIdx.x;
    if (i < n4) g_acc[i] = 0.0f;
    if (i == 0) g_idx_is64 = 0;
}

// Parallel dtype detection: inspect the last 2048 of the first N int32 words
// (in-bounds for both int32[N] and int64[N] layouts). Sorted indices < R are
// never zero there for int32; for int64 every odd word (high half) is zero.
__global__ void detect_idx_kernel(const int* __restrict__ words, int n_words_safe) {
    int end = n_words_safe;
    int start = end - 2048; if (start < 0) start = 0;
    int i = start + blockIdx.x * blockDim.x + threadIdx.x;
    int z = (i < end && words[i] == 0) ? 1 : 0;
    unsigned any = __ballot_sync(0xFFFFFFFFu, z);
    if ((threadIdx.x & 31) == 0 && any) atomicOr(&g_idx_is64, 1);
}

// --- main fused pass: half-warp per sample, L == 64 -------------------------
__global__ __launch_bounds__(512) void shade_kernel(
        const float* __restrict__ albedos,
        const float* __restrict__ normals,
        const float* __restrict__ ldir,
        const float* __restrict__ lcol,
        const float* __restrict__ vis,
        const float* __restrict__ weights,
        const void*  __restrict__ ray_idx,
        int N) {
    int gwarp = (blockIdx.x * blockDim.x + threadIdx.x) >> 5;
    int lane  = threadIdx.x & 31;
    int half  = lane >> 4;
    int sub   = lane & 15;
    int s     = gwarp * 2 + half;
    if (s >= N) return;

    const float4* ldp = (const float4*)(ldir + (size_t)s * 192);
    const float4* lcp = (const float4*)(lcol + (size_t)s * 192);
    const float4* vp  = (const float4*)(vis  + (size_t)s * 64);

    // 7 independent LDG.128, evict-streaming (read-once data)
    float4 d0 = __ldcs(&ldp[sub * 3 + 0]);
    float4 d1 = __ldcs(&ldp[sub * 3 + 1]);
    float4 d2 = __ldcs(&ldp[sub * 3 + 2]);
    float4 c0 = __ldcs(&lcp[sub * 3 + 0]);
    float4 c1 = __ldcs(&lcp[sub * 3 + 1]);
    float4 c2 = __ldcs(&lcp[sub * 3 + 2]);
    float4 v  = __ldcs(&vp[sub]);

    float nx = normals[s * 3 + 0];
    float ny = normals[s * 3 + 1];
    float nz = normals[s * 3 + 2];

    float t0 = fmaf(nx, d0.x, fmaf(ny, d0.y, nz * d0.z));
    float t1 = fmaf(nx, d0.w, fmaf(ny, d1.x, nz * d1.y));
    float t2 = fmaf(nx, d1.z, fmaf(ny, d1.w, nz * d2.x));
    float t3 = fmaf(nx, d2.y, fmaf(ny, d2.z, nz * d2.w));

    int cnt = (t0 > 0.f) + (t1 > 0.f) + (t2 > 0.f) + (t3 > 0.f);

    t0 = fminf(fmaxf(t0, 0.f), 1.f) * v.x;
    t1 = fminf(fmaxf(t1, 0.f), 1.f) * v.y;
    t2 = fminf(fmaxf(t2, 0.f), 1.f) * v.z;
    t3 = fminf(fmaxf(t3, 0.f), 1.f) * v.w;

    float s0 = fmaf(t0, c0.x, fmaf(t1, c0.w, fmaf(t2, c1.z, t3 * c2.y)));
    float s1 = fmaf(t0, c0.y, fmaf(t1, c1.x, fmaf(t2, c1.w, t3 * c2.z)));
    float s2 = fmaf(t0, c0.z, fmaf(t1, c1.y, fmaf(t2, c2.x, t3 * c2.w)));

    #pragma unroll
    for (int off = 8; off; off >>= 1) {
        s0  += __shfl_xor_sync(0xFFFFFFFFu, s0,  off);
        s1  += __shfl_xor_sync(0xFFFFFFFFu, s1,  off);
        s2  += __shfl_xor_sync(0xFFFFFFFFu, s2,  off);
        cnt += __shfl_xor_sync(0xFFFFFFFFu, cnt, off);
    }

    if (sub == 0) {
        float c   = (cnt > 0) ? (float)cnt : 1.0f;
        float inv = 1.0f / c;
        float w   = weights[s];
        int r;
        if (g_idx_is64) r = (int)((const long long*)ray_idx)[s];
        else            r = ((const int*)ray_idx)[s];
        float a0 = albedos[s * 3 + 0];
        float a1 = albedos[s * 3 + 1];
        float a2 = albedos[s * 3 + 2];
        atomicAdd(&g_acc[r * 4 + 0], w * a0 * s0 * inv);
        atomicAdd(&g_acc[r * 4 + 1], w * a1 * s1 * inv);
        atomicAdd(&g_acc[r * 4 + 2], w * a2 * s2 * inv);
        atomicAdd(&g_acc[r * 4 + 3], w);
    }
}

__global__ void finalize_kernel(const float* __restrict__ bg,
                                float* __restrict__ out, int R) {
    int r = blockIdx.x * blockDim.x + threadIdx.x;
    if (r >= R) return;
    float aw = g_acc[r * 4 + 3];
    float one_m = 1.0f - aw;
    #pragma unroll
    for (int c = 0; c < 3; ++c) {
        float x = g_acc[r * 4 + c] + bg[r * 3 + c] * one_m;
        float safe = fmaxf(x, 1e-8f);
        float y = (x <= 0.0031308f) ? (12.92f * x)
                                    : (1.055f * powf(safe, 1.0f / 2.4f) - 0.055f);
        out[r * 3 + c] = y;
    }
}

// Fallback for L != 64
__global__ void shade_kernel_generic(
        const float* __restrict__ albedos,
        const float* __restrict__ normals,
        const float* __restrict__ ldir,
        const float* __restrict__ lcol,
        const float* __restrict__ vis,
        const float* __restrict__ weights,
        const void*  __restrict__ ray_idx,
        int N, int L) {
    int gwarp = (blockIdx.x * blockDim.x + threadIdx.x) >> 5;
    int lane  = threadIdx.x & 31;
    if (gwarp >= N) return;
    float nx = normals[gwarp * 3 + 0];
    float ny = normals[gwarp * 3 + 1];
    float nz = normals[gwarp * 3 + 2];
    const float* ldp = ldir + (size_t)gwarp * L * 3;
    const float* lcp = lcol + (size_t)gwarp * L * 3;
    const float* vp  = vis  + (size_t)gwarp * L;
    float s0 = 0.f, s1 = 0.f, s2 = 0.f;
    int cnt = 0;
    for (int j = lane; j < L; j += 32) {
        float dx = ldp[j * 3 + 0], dy = ldp[j * 3 + 1], dz = ldp[j * 3 + 2];
        float d  = fmaf(nx, dx, fmaf(ny, dy, nz * dz));
        cnt += (d > 0.f) ? 1 : 0;
        d = fminf(fmaxf(d, 0.f), 1.f);
        float dv = d * vp[j];
        s0 = fmaf(dv, lcp[j * 3 + 0], s0);
        s1 = fmaf(dv, lcp[j * 3 + 1], s1);
        s2 = fmaf(dv, lcp[j * 3 + 2], s2);
    }
    #pragma unroll
    for (int off = 16; off; off >>= 1) {
        s0  += __shfl_xor_sync(0xFFFFFFFFu, s0,  off);
        s1  += __shfl_xor_sync(0xFFFFFFFFu, s1,  off);
        s2  += __shfl_xor_sync(0xFFFFFFFFu, s2,  off);
        cnt += __shfl_xor_sync(0xFFFFFFFFu, cnt, off);
    }
    if (lane == 0) {
        float c   = (cnt > 0) ? (float)cnt : 1.0f;
        float inv = 1.0f / c;
        float w   = weights[gwarp];
        int r;
        if (g_idx_is64) r = (int)((const long long*)ray_idx)[gwarp];
        else            r = ((const int*)ray_idx)[gwarp];
        atomicAdd(&g_acc[r * 4 + 0], w * albedos[gwarp * 3 + 0] * s0 * inv);
        atomicAdd(&g_acc[r * 4 + 1], w * albedos[gwarp * 3 + 1] * s1 * inv);
        atomicAdd(&g_acc[r * 4 + 2], w * albedos[gwarp * 3 + 2] * s2 * inv);
        atomicAdd(&g_acc[r * 4 + 3], w);
    }
}

extern "C" void kernel_launch(void* const* d_in, const int* in_sizes, int n_in,
                              void* d_out, int out_size) {
    const float* albedos = (const float*)d_in[0];
    const float* normals = (const float*)d_in[1];
    const float* ldir    = (const float*)d_in[2];
    const float* lcol    = (const float*)d_in[3];
    const float* vis     = (const float*)d_in[4];
    const float* bg      = (const float*)d_in[5];
    const float* weights = (const float*)d_in[6];
    const void*  ray_idx = (const void*) d_in[7];
    float* out = (float*)d_out;

    int N = in_sizes[0] / 3;
    int L = (N > 0) ? in_sizes[2] / (N * 3) : 1;
    int R = out_size / 3;
    if (R > MAX_RAYS) R = MAX_RAYS;

    // 1) zero accumulators + detection flag
    int n4 = R * 4;
    zero_acc_kernel<<<(n4 + 255) / 256, 256>>>(n4);

    // 2) parallel dtype detection (2048 words / 1024 threads / 2 blocks)
    detect_idx_kernel<<<2, 1024>>>((const int*)ray_idx, in_sizes[7]);

    // 3) fused shade + scatter
    if (L == 64) {
        int samples_per_block = 32;            // 512 threads = 16 warps = 32 samples
        int blocks = (N + samples_per_block - 1) / samples_per_block;
        shade_kernel<<<blocks, 512>>>(
            albedos, normals, ldir, lcol, vis, weights, ray_idx, N);
    } else {
        int blocks = (N + 7) / 8;
        shade_kernel_generic<<<blocks, 256>>>(
            albedos, normals, ldir, lcol, vis, weights, ray_idx, N, L);
    }

    // 4) blend + sRGB
    finalize_kernel<<<(R + 255) / 256, 256>>>(bg, out, R);
}